// round 3
// baseline (speedup 1.0000x reference)
#include <cuda_runtime.h>

// CategoryAwareGate: B=8, C=16, H=W=256, HID=32, N = B*H*W = 524288.
// Outputs packed in d_out (float32): fused_logits[8,16,256,256] (8388608),
// expert_preferences[16,2] (32), dynamic_weights[N,16,2] (16777216).
//
// Per pixel n, class c:
//   sp = softmax_C(swin)[c], gp = softmax_C(gru)[c]     (no max-sub: |logit| small)
//   hid_h = relu(W1[c,h,0]*sp + W1[c,h,1]*gp + b1[c,h])
//   d = (b2[c,0]-b2[c,1]) + sum_h (W2[c,0,h]-W2[c,1,h])*hid_h   // z0 - z1
//   dw0 = sigmoid(d); dw1 = 1 - dw0; fused[c] = gl + dw0*(sl-gl)
//
// R3: 1 pixel/thread, <=64 regs, 4 CTAs/SM (32 warps). exp() computed once and
// staged in smem rows; dw float4 overwrites the consumed exp slots; coalesced
// warp-transposed drain. sl/gl reloaded from L1 for the fusion epilogue.

static constexpr long FUSED_ELEMS = 8L * 16 * 65536;  // 8388608
static constexpr int TB_STRIDE = 36;                  // floats/row: conflict-free .128
static constexpr int SMEM_BYTES = 8192 + 64 + 256 * TB_STRIDE * 4;  // 45120

__device__ __forceinline__ unsigned long long pk2(float a, float b) {
    unsigned long long r;
    asm("mov.b64 %0, {%1, %2};" : "=l"(r) : "f"(a), "f"(b));
    return r;
}
__device__ __forceinline__ void upk2(unsigned long long v, float& a, float& b) {
    asm("mov.b64 {%0, %1}, %2;" : "=f"(a), "=f"(b) : "l"(v));
}
__device__ __forceinline__ unsigned long long fma2(unsigned long long a,
                                                   unsigned long long b,
                                                   unsigned long long c) {
    unsigned long long r;
    asm("fma.rn.f32x2 %0, %1, %2, %3;" : "=l"(r) : "l"(a), "l"(b), "l"(c));
    return r;
}
__device__ __forceinline__ unsigned long long mul2(unsigned long long a,
                                                   unsigned long long b) {
    unsigned long long r;
    asm("mul.rn.f32x2 %0, %1, %2;" : "=l"(r) : "l"(a), "l"(b));
    return r;
}

__global__ void __launch_bounds__(256, 4)
gate_fuse_kernel(const float* __restrict__ swin, const float* __restrict__ gru,
                 const float* __restrict__ W1, const float* __restrict__ b1,
                 const float* __restrict__ W2, const float* __restrict__ b2,
                 float* __restrict__ fused, float* __restrict__ dw) {
    extern __shared__ __align__(16) unsigned char smem_raw[];
    unsigned long long* sw = reinterpret_cast<unsigned long long*>(smem_raw);  // 1024 u64
    float* sb2d = reinterpret_cast<float*>(smem_raw + 8192);                   // 16 floats
    float* tb   = reinterpret_cast<float*>(smem_raw + 8192 + 64);              // 256 rows x 36

    const int tid = threadIdx.x;
    const int warp = tid >> 5;
    const int lane = tid & 31;

    // Pack per-(class-pair p, h): [w10 pair][w11 pair][b1 pair][w2diff pair]
    {
        const int p = tid >> 5, h = tid & 31;  // 8*32 == blockDim
        const int c0 = p * 2, c1 = c0 + 1;
        // W1:(C,32,2) c*64+h*2+i ; b1:(C,32) ; W2:(C,2,32) c*64+o*32+h
        sw[tid * 4 + 0] = pk2(W1[c0 * 64 + h * 2 + 0], W1[c1 * 64 + h * 2 + 0]);
        sw[tid * 4 + 1] = pk2(W1[c0 * 64 + h * 2 + 1], W1[c1 * 64 + h * 2 + 1]);
        sw[tid * 4 + 2] = pk2(b1[c0 * 32 + h], b1[c1 * 32 + h]);
        sw[tid * 4 + 3] = pk2(W2[c0 * 64 + h] - W2[c0 * 64 + 32 + h],
                              W2[c1 * 64 + h] - W2[c1 * 64 + 32 + h]);
    }
    if (tid < 16) sb2d[tid] = b2[tid * 2] - b2[tid * 2 + 1];
    __syncthreads();

    const int n = blockIdx.x * 256 + tid;  // grid 2048*256 = N; block within one image
    const long base = (long)(n >> 16) * (16L * 65536) + (n & 65535);
    float* row = tb + tid * TB_STRIDE;

    // Phase A: exps once, staged into row slots [4p..4p+3] = (es0,es1,eg0,eg1).
    float ss = 0.f, sg = 0.f;
#pragma unroll
    for (int p = 0; p < 8; p++) {
        const long o = base + (long)(2 * p) * 65536;
        const float es0 = __expf(__ldg(swin + o));
        const float es1 = __expf(__ldg(swin + o + 65536));
        const float eg0 = __expf(__ldg(gru + o));
        const float eg1 = __expf(__ldg(gru + o + 65536));
        ss += es0 + es1;
        sg += eg0 + eg1;
        *reinterpret_cast<float4*>(row + 4 * p) = make_float4(es0, es1, eg0, eg1);
    }
    const unsigned long long rs2 = pk2(__fdividef(1.f, ss), __fdividef(1.f, ss));
    const unsigned long long rg2 = pk2(__fdividef(1.f, sg), __fdividef(1.f, sg));

    for (int p = 0; p < 8; p++) {
        const float4 e = *reinterpret_cast<const float4*>(row + 4 * p);
        const unsigned long long xp = mul2(pk2(e.x, e.y), rs2);
        const unsigned long long yp = mul2(pk2(e.z, e.w), rg2);
        unsigned long long d2 =
            *reinterpret_cast<const unsigned long long*>(sb2d + 2 * p);
        const unsigned long long* wp = sw + p * 128;
#pragma unroll
        for (int h = 0; h < 32; h++) {
            const ulonglong2 wA = *reinterpret_cast<const ulonglong2*>(wp + h * 4);
            const ulonglong2 wB = *reinterpret_cast<const ulonglong2*>(wp + h * 4 + 2);
            unsigned long long t = fma2(wA.x, xp, wB.x);
            t = fma2(wA.y, yp, t);
            float a, b;
            upk2(t, a, b);
            a = fmaxf(a, 0.f);
            b = fmaxf(b, 0.f);
            d2 = fma2(wB.y, pk2(a, b), d2);
        }
        float d0, d1;
        upk2(d2, d0, d1);
        const float w0 = __fdividef(1.f, 1.f + __expf(-d0));
        const float w1 = __fdividef(1.f, 1.f + __expf(-d1));
        // dw overwrites the consumed exp slots (same bank-safe .128 pattern)
        *reinterpret_cast<float4*>(row + 4 * p) =
            make_float4(w0, 1.f - w0, w1, 1.f - w1);
        // fusion epilogue: reload logits (L1/L2 hits), coalesced per class plane
        const long o = base + (long)(2 * p) * 65536;
        const float sl0 = __ldg(swin + o), gl0 = __ldg(gru + o);
        const float sl1 = __ldg(swin + o + 65536), gl1 = __ldg(gru + o + 65536);
        fused[o] = fmaf(w0, sl0 - gl0, gl0);
        fused[o + 65536] = fmaf(w1, sl1 - gl1, gl1);
    }

    __syncwarp();
    // Coalesced drain: this warp's 32 pixels x 32 floats = 4KB contiguous in dw.
    {
        float* wrows = tb + warp * 32 * TB_STRIDE;
        const long g = ((long)blockIdx.x * 256 + warp * 32) * 32;
#pragma unroll
        for (int k = 0; k < 8; k++) {
            const int pix = 4 * k + (lane >> 3);
            const int elem = (lane & 7) * 4;
            const float4 v =
                *reinterpret_cast<const float4*>(wrows + pix * TB_STRIDE + elem);
            *reinterpret_cast<float4*>(dw + g + k * 128 + lane * 4) = v;
        }
    }
}

extern "C" void kernel_launch(void* const* d_in, const int* in_sizes, int n_in,
                              void* d_out, int out_size) {
    const float* swin = (const float*)d_in[0];
    const float* gru  = (const float*)d_in[1];
    const float* W1   = (const float*)d_in[2];
    const float* b1   = (const float*)d_in[3];
    const float* W2   = (const float*)d_in[4];
    const float* b2   = (const float*)d_in[5];
    const float* pref = (const float*)d_in[6];

    float* out     = (float*)d_out;
    float* fusedp  = out;                     // 8388608
    float* prefout = out + FUSED_ELEMS;       // 32
    float* dwp     = out + FUSED_ELEMS + 32;  // 16777216

    cudaFuncSetAttribute(gate_fuse_kernel,
                         cudaFuncAttributeMaxDynamicSharedMemorySize, SMEM_BYTES);
    cudaMemcpyAsync(prefout, pref, 32 * sizeof(float), cudaMemcpyDeviceToDevice);
    gate_fuse_kernel<<<2048, 256, SMEM_BYTES>>>(swin, gru, W1, b1, W2, b2, fusedp, dwp);
}

// round 5
// speedup vs baseline: 1.1134x; 1.1134x over previous
#include <cuda_runtime.h>

// CategoryAwareGate: B=8, C=16, H=W=256, HID=32, N = B*H*W = 524288.
// d_out packing (float32): fused_logits[8,16,256,256] (8388608),
// expert_preferences[16,2] (32), dynamic_weights[N,16,2] (16777216).
//
// R5 (= R4 with alignment fix): 4 pixel-slots per thread (one weight-LDS pass
// serves 4 pixels). Logits reloaded from L2 per pair (feeds exp recompute +
// fused epilogue). dw staged as (w0,w1) in stride-18 smem rows (8B-aligned,
// bank-conflict-free); 1-w reconstructed at the coalesced drain. p-loop rolled
// to stay I$-resident. 2 CTAs/SM.

static constexpr long FUSED_ELEMS = 8L * 16 * 65536;  // 8388608
static constexpr int STR = 18;  // floats per w-row (16 + 2 pad): even -> float2 aligned
static constexpr int SMEM_BYTES = 8192 + 64 + 4 * 256 * STR * 4;  // 81984

__device__ __forceinline__ unsigned long long pk2(float a, float b) {
    unsigned long long r;
    asm("mov.b64 %0, {%1, %2};" : "=l"(r) : "f"(a), "f"(b));
    return r;
}
__device__ __forceinline__ void upk2(unsigned long long v, float& a, float& b) {
    asm("mov.b64 {%0, %1}, %2;" : "=f"(a), "=f"(b) : "l"(v));
}
__device__ __forceinline__ unsigned long long fma2(unsigned long long a,
                                                   unsigned long long b,
                                                   unsigned long long c) {
    unsigned long long r;
    asm("fma.rn.f32x2 %0, %1, %2, %3;" : "=l"(r) : "l"(a), "l"(b), "l"(c));
    return r;
}

__global__ void __launch_bounds__(256, 2)
gate_fuse_kernel(const float* __restrict__ swin, const float* __restrict__ gru,
                 const float* __restrict__ W1, const float* __restrict__ b1,
                 const float* __restrict__ W2, const float* __restrict__ b2,
                 float* __restrict__ fused, float* __restrict__ dw) {
    extern __shared__ __align__(16) unsigned char smem_raw[];
    unsigned long long* sw = reinterpret_cast<unsigned long long*>(smem_raw);  // 1024 u64
    float* sb2d = reinterpret_cast<float*>(smem_raw + 8192);                   // 16 floats
    float* wbuf = reinterpret_cast<float*>(smem_raw + 8192 + 64);              // 1024 x 18

    const int tid = threadIdx.x;
    const int warp = tid >> 5;
    const int lane = tid & 31;

    // Pack per-(class-pair p, h): [w10 pair][w11 pair][b1 pair][w2diff pair]
    {
        const int p = tid >> 5, h = tid & 31;  // 8*32 == blockDim
        const int c0 = p * 2, c1 = c0 + 1;
        // W1:(C,32,2) c*64+h*2+i ; b1:(C,32) ; W2:(C,2,32) c*64+o*32+h
        sw[tid * 4 + 0] = pk2(W1[c0 * 64 + h * 2 + 0], W1[c1 * 64 + h * 2 + 0]);
        sw[tid * 4 + 1] = pk2(W1[c0 * 64 + h * 2 + 1], W1[c1 * 64 + h * 2 + 1]);
        sw[tid * 4 + 2] = pk2(b1[c0 * 32 + h], b1[c1 * 32 + h]);
        sw[tid * 4 + 3] = pk2(W2[c0 * 64 + h] - W2[c0 * 64 + 32 + h],
                              W2[c1 * 64 + h] - W2[c1 * 64 + 32 + h]);
    }
    if (tid < 16) sb2d[tid] = b2[tid * 2] - b2[tid * 2 + 1];
    __syncthreads();

    // Block = 1024 consecutive pixels (64 blocks per image -> never straddles).
    // Slot s pixel: n0 + s*256.
    const int n0 = blockIdx.x * 1024 + tid;
    const long base = (long)(n0 >> 16) * (16L * 65536) + (n0 & 65535);

    // Phase A: softmax denominators only (exps recomputed per pair later).
    float rs[4], rg[4];
#pragma unroll
    for (int s = 0; s < 4; s++) {
        const long bs = base + s * 256;
        float ss = 0.f, sg = 0.f;
#pragma unroll
        for (int c = 0; c < 16; c++) {
            ss += __expf(__ldg(swin + bs + (long)c * 65536));
            sg += __expf(__ldg(gru + bs + (long)c * 65536));
        }
        rs[s] = __fdividef(1.f, ss);
        rg[s] = __fdividef(1.f, sg);
    }

    float* myrow = wbuf + tid * STR;  // rows: [slot*256 + tid]

#pragma unroll 1
    for (int p = 0; p < 8; p++) {
        const unsigned long long d2i =
            *reinterpret_cast<const unsigned long long*>(sb2d + 2 * p);
        const long po = base + (long)(2 * p) * 65536;

        // Reload logits (L1/L2 hits) for exp recompute + fused epilogue.
        float sl0[4], sl1[4], gl0[4], gl1[4];
        unsigned long long xp[4], yp[4], d2[4];
#pragma unroll
        for (int s = 0; s < 4; s++) {
            const long o = po + s * 256;
            sl0[s] = __ldg(swin + o);
            sl1[s] = __ldg(swin + o + 65536);
            gl0[s] = __ldg(gru + o);
            gl1[s] = __ldg(gru + o + 65536);
            xp[s] = pk2(__expf(sl0[s]) * rs[s], __expf(sl1[s]) * rs[s]);
            yp[s] = pk2(__expf(gl0[s]) * rg[s], __expf(gl1[s]) * rg[s]);
            d2[s] = d2i;
        }

        const unsigned long long* wp = sw + p * 128;
#pragma unroll
        for (int h = 0; h < 32; h++) {
            const ulonglong2 wA = *reinterpret_cast<const ulonglong2*>(wp + h * 4);
            const ulonglong2 wB = *reinterpret_cast<const ulonglong2*>(wp + h * 4 + 2);
#pragma unroll
            for (int s = 0; s < 4; s++) {
                unsigned long long t = fma2(wA.x, xp[s], wB.x);
                t = fma2(wA.y, yp[s], t);
                float a, b;
                upk2(t, a, b);
                a = fmaxf(a, 0.f);
                b = fmaxf(b, 0.f);
                d2[s] = fma2(wB.y, pk2(a, b), d2[s]);
            }
        }

#pragma unroll
        for (int s = 0; s < 4; s++) {
            float d0, d1;
            upk2(d2[s], d0, d1);
            const float w0 = __fdividef(1.f, 1.f + __expf(-d0));
            const float w1 = __fdividef(1.f, 1.f + __expf(-d1));
            *reinterpret_cast<float2*>(myrow + s * 256 * STR + 2 * p) =
                make_float2(w0, w1);
            const long o = po + s * 256;
            fused[o] = fmaf(w0, sl0[s] - gl0[s], gl0[s]);
            fused[o + 65536] = fmaf(w1, sl1[s] - gl1[s], gl1[s]);
        }
    }

    __syncwarp();  // drain reads only this warp's own rows
    // Drain: per (slot, warp): 32 px * 32 floats = 4KB contiguous in dw.
#pragma unroll
    for (int s = 0; s < 4; s++) {
        const float* rows = wbuf + (s * 256 + warp * 32) * STR;
        const long g = ((long)blockIdx.x * 1024 + s * 256 + warp * 32) * 32;
#pragma unroll
        for (int k = 0; k < 8; k++) {
            const int px = 4 * k + (lane >> 3);
            const int pr = lane & 7;
            const float2 w =
                *reinterpret_cast<const float2*>(rows + px * STR + pr * 2);
            *reinterpret_cast<float4*>(dw + g + k * 128 + lane * 4) =
                make_float4(w.x, 1.f - w.x, w.y, 1.f - w.y);
        }
    }
}

extern "C" void kernel_launch(void* const* d_in, const int* in_sizes, int n_in,
                              void* d_out, int out_size) {
    const float* swin = (const float*)d_in[0];
    const float* gru  = (const float*)d_in[1];
    const float* W1   = (const float*)d_in[2];
    const float* b1   = (const float*)d_in[3];
    const float* W2   = (const float*)d_in[4];
    const float* b2   = (const float*)d_in[5];
    const float* pref = (const float*)d_in[6];

    float* out     = (float*)d_out;
    float* fusedp  = out;                     // 8388608
    float* prefout = out + FUSED_ELEMS;       // 32
    float* dwp     = out + FUSED_ELEMS + 32;  // 16777216

    cudaFuncSetAttribute(gate_fuse_kernel,
                         cudaFuncAttributeMaxDynamicSharedMemorySize, SMEM_BYTES);
    cudaMemcpyAsync(prefout, pref, 32 * sizeof(float), cudaMemcpyDeviceToDevice);
    gate_fuse_kernel<<<512, 256, SMEM_BYTES>>>(swin, gru, W1, b1, W2, b2, fusedp, dwp);
}

// round 7
// speedup vs baseline: 1.2110x; 1.0877x over previous
#include <cuda_runtime.h>

// CategoryAwareGate: B=8, C=16, H=W=256, HID=32, N = B*H*W = 524288.
// d_out packing (float32): fused_logits[8,16,256,256] (8388608),
// expert_preferences[16,2] (32), dynamic_weights[N,16,2] (16777216).
//
// R7: block=128, 4 pixel-slots/thread, 5 CTAs/SM target (regs<=102, smem 45KB).
// Packed-f32x2 MLP; relu via paired scalar max.f32 inside one asm block.
// dw staged in stride-18 smem rows, coalesced drain. p-loop rolled.

static constexpr long FUSED_ELEMS = 8L * 16 * 65536;  // 8388608
static constexpr int STR = 18;                         // floats per w-row
static constexpr int SMEM_BYTES = 8192 + 64 + 512 * STR * 4;  // 45120

__device__ __forceinline__ unsigned long long pk2(float a, float b) {
    unsigned long long r;
    asm("mov.b64 %0, {%1, %2};" : "=l"(r) : "f"(a), "f"(b));
    return r;
}
__device__ __forceinline__ void upk2(unsigned long long v, float& a, float& b) {
    asm("mov.b64 {%0, %1}, %2;" : "=f"(a), "=f"(b) : "l"(v));
}
__device__ __forceinline__ unsigned long long fma2(unsigned long long a,
                                                   unsigned long long b,
                                                   unsigned long long c) {
    unsigned long long r;
    asm("fma.rn.f32x2 %0, %1, %2, %3;" : "=l"(r) : "l"(a), "l"(b), "l"(c));
    return r;
}
// packed relu: two scalar max.f32 on the halves (no f32x2 min/max in PTX)
__device__ __forceinline__ unsigned long long relu2(unsigned long long v) {
    unsigned long long r;
    asm("{\n\t"
        ".reg .f32 lo, hi;\n\t"
        "mov.b64 {lo, hi}, %1;\n\t"
        "max.f32 lo, lo, 0f00000000;\n\t"
        "max.f32 hi, hi, 0f00000000;\n\t"
        "mov.b64 %0, {lo, hi};\n\t"
        "}" : "=l"(r) : "l"(v));
    return r;
}

__global__ void __launch_bounds__(128, 5)
gate_fuse_kernel(const float* __restrict__ swin, const float* __restrict__ gru,
                 const float* __restrict__ W1, const float* __restrict__ b1,
                 const float* __restrict__ W2, const float* __restrict__ b2,
                 float* __restrict__ fused, float* __restrict__ dw) {
    extern __shared__ __align__(16) unsigned char smem_raw[];
    unsigned long long* sw = reinterpret_cast<unsigned long long*>(smem_raw);  // 1024 u64
    float* sb2d = reinterpret_cast<float*>(smem_raw + 8192);                   // 16 floats
    float* wbuf = reinterpret_cast<float*>(smem_raw + 8192 + 64);              // 512 x 18

    const int tid = threadIdx.x;
    const int warp = tid >> 5;
    const int lane = tid & 31;

    // Pack per-(class-pair p, h): [w10 pair][w11 pair][b1 pair][w2diff pair]
    for (int idx = tid; idx < 256; idx += 128) {
        const int p = idx >> 5, h = idx & 31;
        const int c0 = p * 2, c1 = c0 + 1;
        // W1:(C,32,2) c*64+h*2+i ; b1:(C,32) ; W2:(C,2,32) c*64+o*32+h
        sw[idx * 4 + 0] = pk2(W1[c0 * 64 + h * 2 + 0], W1[c1 * 64 + h * 2 + 0]);
        sw[idx * 4 + 1] = pk2(W1[c0 * 64 + h * 2 + 1], W1[c1 * 64 + h * 2 + 1]);
        sw[idx * 4 + 2] = pk2(b1[c0 * 32 + h], b1[c1 * 32 + h]);
        sw[idx * 4 + 3] = pk2(W2[c0 * 64 + h] - W2[c0 * 64 + 32 + h],
                              W2[c1 * 64 + h] - W2[c1 * 64 + 32 + h]);
    }
    if (tid < 16) sb2d[tid] = b2[tid * 2] - b2[tid * 2 + 1];
    __syncthreads();

    // Block = 512 consecutive pixels (128 blocks/image: never straddles).
    const int n0 = blockIdx.x * 512 + tid;  // slot s pixel: n0 + s*128
    const long base = (long)(n0 >> 16) * (16L * 65536) + (n0 & 65535);

    // Phase A: softmax denominators (exps recomputed per pair later).
    float rs[4], rg[4];
#pragma unroll
    for (int s = 0; s < 4; s++) {
        const long bs = base + s * 128;
        float ss = 0.f, sg = 0.f;
#pragma unroll
        for (int c = 0; c < 16; c++) {
            ss += __expf(__ldg(swin + bs + (long)c * 65536));
            sg += __expf(__ldg(gru + bs + (long)c * 65536));
        }
        rs[s] = __fdividef(1.f, ss);
        rg[s] = __fdividef(1.f, sg);
    }

    float* myrow = wbuf + tid * STR;  // rows: [slot*128 + tid]

#pragma unroll 1
    for (int p = 0; p < 8; p++) {
        const unsigned long long d2i =
            *reinterpret_cast<const unsigned long long*>(sb2d + 2 * p);
        const long po = base + (long)(2 * p) * 65536;

        float sl0[4], sl1[4], gl0[4], gl1[4];
        unsigned long long xp[4], yp[4], d2[4];
#pragma unroll
        for (int s = 0; s < 4; s++) {
            const long o = po + s * 128;
            sl0[s] = __ldg(swin + o);
            sl1[s] = __ldg(swin + o + 65536);
            gl0[s] = __ldg(gru + o);
            gl1[s] = __ldg(gru + o + 65536);
            xp[s] = pk2(__expf(sl0[s]) * rs[s], __expf(sl1[s]) * rs[s]);
            yp[s] = pk2(__expf(gl0[s]) * rg[s], __expf(gl1[s]) * rg[s]);
            d2[s] = d2i;
        }

        const unsigned long long* wp = sw + p * 128;
#pragma unroll
        for (int h = 0; h < 32; h++) {
            const ulonglong2 wA = *reinterpret_cast<const ulonglong2*>(wp + h * 4);
            const ulonglong2 wB = *reinterpret_cast<const ulonglong2*>(wp + h * 4 + 2);
#pragma unroll
            for (int s = 0; s < 4; s++) {
                unsigned long long t = fma2(wA.x, xp[s], wB.x);
                t = fma2(wA.y, yp[s], t);
                d2[s] = fma2(wB.y, relu2(t), d2[s]);
            }
        }

#pragma unroll
        for (int s = 0; s < 4; s++) {
            float d0, d1;
            upk2(d2[s], d0, d1);
            const float w0 = __fdividef(1.f, 1.f + __expf(-d0));
            const float w1 = __fdividef(1.f, 1.f + __expf(-d1));
            *reinterpret_cast<float2*>(myrow + s * 128 * STR + 2 * p) =
                make_float2(w0, w1);
            const long o = po + s * 128;
            fused[o] = fmaf(w0, sl0[s] - gl0[s], gl0[s]);
            fused[o + 65536] = fmaf(w1, sl1[s] - gl1[s], gl1[s]);
        }
    }

    __syncwarp();  // drain reads only this warp's own rows
    // Drain: per (slot, warp): 32 px * 32 floats = 4KB contiguous in dw.
#pragma unroll
    for (int s = 0; s < 4; s++) {
        const float* rows = wbuf + (s * 128 + warp * 32) * STR;
        const long g = ((long)blockIdx.x * 512 + s * 128 + warp * 32) * 32;
#pragma unroll
        for (int k = 0; k < 8; k++) {
            const int px = 4 * k + (lane >> 3);
            const int pr = lane & 7;
            const float2 w =
                *reinterpret_cast<const float2*>(rows + px * STR + pr * 2);
            *reinterpret_cast<float4*>(dw + g + k * 128 + lane * 4) =
                make_float4(w.x, 1.f - w.x, w.y, 1.f - w.y);
        }
    }
}

extern "C" void kernel_launch(void* const* d_in, const int* in_sizes, int n_in,
                              void* d_out, int out_size) {
    const float* swin = (const float*)d_in[0];
    const float* gru  = (const float*)d_in[1];
    const float* W1   = (const float*)d_in[2];
    const float* b1   = (const float*)d_in[3];
    const float* W2   = (const float*)d_in[4];
    const float* b2   = (const float*)d_in[5];
    const float* pref = (const float*)d_in[6];

    float* out     = (float*)d_out;
    float* fusedp  = out;                     // 8388608
    float* prefout = out + FUSED_ELEMS;       // 32
    float* dwp     = out + FUSED_ELEMS + 32;  // 16777216

    cudaFuncSetAttribute(gate_fuse_kernel,
                         cudaFuncAttributeMaxDynamicSharedMemorySize, SMEM_BYTES);
    cudaMemcpyAsync(prefout, pref, 32 * sizeof(float), cudaMemcpyDeviceToDevice);
    gate_fuse_kernel<<<1024, 128, SMEM_BYTES>>>(swin, gru, W1, b1, W2, b2, fusedp, dwp);
}

// round 8
// speedup vs baseline: 1.2915x; 1.0665x over previous
#include <cuda_runtime.h>

// CategoryAwareGate: B=8, C=16, H=W=256, HID=32, N = B*H*W = 524288.
// d_out packing (float32): fused_logits[8,16,256,256] (8388608),
// expert_preferences[16,2] (32), dynamic_weights[N,16,2] (16777216).
//
// R8: block=128, 2 pixel-slots/thread, 7 CTAs/SM (regs<=73, smem 26.7KB).
// grid=2048 -> 1.98 waves at 1036 concurrent CTAs (no tail waste).
// Packed-f32x2 MLP; relu via paired scalar max.f32. dw staged in stride-18
// smem rows, coalesced drain. p-loop rolled.

static constexpr long FUSED_ELEMS = 8L * 16 * 65536;  // 8388608
static constexpr int STR = 18;                         // floats per w-row
static constexpr int SMEM_BYTES = 8192 + 64 + 256 * STR * 4;  // 26688

__device__ __forceinline__ unsigned long long pk2(float a, float b) {
    unsigned long long r;
    asm("mov.b64 %0, {%1, %2};" : "=l"(r) : "f"(a), "f"(b));
    return r;
}
__device__ __forceinline__ void upk2(unsigned long long v, float& a, float& b) {
    asm("mov.b64 {%0, %1}, %2;" : "=f"(a), "=f"(b) : "l"(v));
}
__device__ __forceinline__ unsigned long long fma2(unsigned long long a,
                                                   unsigned long long b,
                                                   unsigned long long c) {
    unsigned long long r;
    asm("fma.rn.f32x2 %0, %1, %2, %3;" : "=l"(r) : "l"(a), "l"(b), "l"(c));
    return r;
}
// packed relu: two scalar max.f32 on the halves (no f32x2 min/max in PTX)
__device__ __forceinline__ unsigned long long relu2(unsigned long long v) {
    unsigned long long r;
    asm("{\n\t"
        ".reg .f32 lo, hi;\n\t"
        "mov.b64 {lo, hi}, %1;\n\t"
        "max.f32 lo, lo, 0f00000000;\n\t"
        "max.f32 hi, hi, 0f00000000;\n\t"
        "mov.b64 %0, {lo, hi};\n\t"
        "}" : "=l"(r) : "l"(v));
    return r;
}

__global__ void __launch_bounds__(128, 7)
gate_fuse_kernel(const float* __restrict__ swin, const float* __restrict__ gru,
                 const float* __restrict__ W1, const float* __restrict__ b1,
                 const float* __restrict__ W2, const float* __restrict__ b2,
                 float* __restrict__ fused, float* __restrict__ dw) {
    extern __shared__ __align__(16) unsigned char smem_raw[];
    unsigned long long* sw = reinterpret_cast<unsigned long long*>(smem_raw);  // 1024 u64
    float* sb2d = reinterpret_cast<float*>(smem_raw + 8192);                   // 16 floats
    float* wbuf = reinterpret_cast<float*>(smem_raw + 8192 + 64);              // 256 x 18

    const int tid = threadIdx.x;
    const int warp = tid >> 5;
    const int lane = tid & 31;

    // Pack per-(class-pair p, h): [w10 pair][w11 pair][b1 pair][w2diff pair]
    for (int idx = tid; idx < 256; idx += 128) {
        const int p = idx >> 5, h = idx & 31;
        const int c0 = p * 2, c1 = c0 + 1;
        // W1:(C,32,2) c*64+h*2+i ; b1:(C,32) ; W2:(C,2,32) c*64+o*32+h
        sw[idx * 4 + 0] = pk2(W1[c0 * 64 + h * 2 + 0], W1[c1 * 64 + h * 2 + 0]);
        sw[idx * 4 + 1] = pk2(W1[c0 * 64 + h * 2 + 1], W1[c1 * 64 + h * 2 + 1]);
        sw[idx * 4 + 2] = pk2(b1[c0 * 32 + h], b1[c1 * 32 + h]);
        sw[idx * 4 + 3] = pk2(W2[c0 * 64 + h] - W2[c0 * 64 + 32 + h],
                              W2[c1 * 64 + h] - W2[c1 * 64 + 32 + h]);
    }
    if (tid < 16) sb2d[tid] = b2[tid * 2] - b2[tid * 2 + 1];
    __syncthreads();

    // Block = 256 consecutive pixels (256 blocks/image: never straddles).
    const int n0 = blockIdx.x * 256 + tid;  // slot s pixel: n0 + s*128
    const long base = (long)(n0 >> 16) * (16L * 65536) + (n0 & 65535);

    // Phase A: softmax denominators (exps recomputed per pair later).
    float rs[2], rg[2];
#pragma unroll
    for (int s = 0; s < 2; s++) {
        const long bs = base + s * 128;
        float ss = 0.f, sg = 0.f;
#pragma unroll
        for (int c = 0; c < 16; c++) {
            ss += __expf(__ldg(swin + bs + (long)c * 65536));
            sg += __expf(__ldg(gru + bs + (long)c * 65536));
        }
        rs[s] = __fdividef(1.f, ss);
        rg[s] = __fdividef(1.f, sg);
    }

    float* myrow = wbuf + tid * STR;  // rows: [slot*128 + tid]

#pragma unroll 1
    for (int p = 0; p < 8; p++) {
        const unsigned long long d2i =
            *reinterpret_cast<const unsigned long long*>(sb2d + 2 * p);
        const long po = base + (long)(2 * p) * 65536;

        float sl0[2], sl1[2], gl0[2], gl1[2];
        unsigned long long xp[2], yp[2], d2[2];
#pragma unroll
        for (int s = 0; s < 2; s++) {
            const long o = po + s * 128;
            sl0[s] = __ldg(swin + o);
            sl1[s] = __ldg(swin + o + 65536);
            gl0[s] = __ldg(gru + o);
            gl1[s] = __ldg(gru + o + 65536);
            xp[s] = pk2(__expf(sl0[s]) * rs[s], __expf(sl1[s]) * rs[s]);
            yp[s] = pk2(__expf(gl0[s]) * rg[s], __expf(gl1[s]) * rg[s]);
            d2[s] = d2i;
        }

        const unsigned long long* wp = sw + p * 128;
#pragma unroll
        for (int h = 0; h < 32; h++) {
            const ulonglong2 wA = *reinterpret_cast<const ulonglong2*>(wp + h * 4);
            const ulonglong2 wB = *reinterpret_cast<const ulonglong2*>(wp + h * 4 + 2);
#pragma unroll
            for (int s = 0; s < 2; s++) {
                unsigned long long t = fma2(wA.x, xp[s], wB.x);
                t = fma2(wA.y, yp[s], t);
                d2[s] = fma2(wB.y, relu2(t), d2[s]);
            }
        }

#pragma unroll
        for (int s = 0; s < 2; s++) {
            float d0, d1;
            upk2(d2[s], d0, d1);
            const float w0 = __fdividef(1.f, 1.f + __expf(-d0));
            const float w1 = __fdividef(1.f, 1.f + __expf(-d1));
            *reinterpret_cast<float2*>(myrow + s * 128 * STR + 2 * p) =
                make_float2(w0, w1);
            const long o = po + s * 128;
            fused[o] = fmaf(w0, sl0[s] - gl0[s], gl0[s]);
            fused[o + 65536] = fmaf(w1, sl1[s] - gl1[s], gl1[s]);
        }
    }

    __syncwarp();  // drain reads only this warp's own rows
    // Drain: per (slot, warp): 32 px * 32 floats = 4KB contiguous in dw.
#pragma unroll
    for (int s = 0; s < 2; s++) {
        const float* rows = wbuf + (s * 128 + warp * 32) * STR;
        const long g = ((long)blockIdx.x * 256 + s * 128 + warp * 32) * 32;
#pragma unroll
        for (int k = 0; k < 8; k++) {
            const int px = 4 * k + (lane >> 3);
            const int pr = lane & 7;
            const float2 w =
                *reinterpret_cast<const float2*>(rows + px * STR + pr * 2);
            *reinterpret_cast<float4*>(dw + g + k * 128 + lane * 4) =
                make_float4(w.x, 1.f - w.x, w.y, 1.f - w.y);
        }
    }
}

extern "C" void kernel_launch(void* const* d_in, const int* in_sizes, int n_in,
                              void* d_out, int out_size) {
    const float* swin = (const float*)d_in[0];
    const float* gru  = (const float*)d_in[1];
    const float* W1   = (const float*)d_in[2];
    const float* b1   = (const float*)d_in[3];
    const float* W2   = (const float*)d_in[4];
    const float* b2   = (const float*)d_in[5];
    const float* pref = (const float*)d_in[6];

    float* out     = (float*)d_out;
    float* fusedp  = out;                     // 8388608
    float* prefout = out + FUSED_ELEMS;       // 32
    float* dwp     = out + FUSED_ELEMS + 32;  // 16777216

    cudaFuncSetAttribute(gate_fuse_kernel,
                         cudaFuncAttributeMaxDynamicSharedMemorySize, SMEM_BYTES);
    cudaMemcpyAsync(prefout, pref, 32 * sizeof(float), cudaMemcpyDeviceToDevice);
    gate_fuse_kernel<<<2048, 128, SMEM_BYTES>>>(swin, gru, W1, b1, W2, b2, fusedp, dwp);
}